// round 15
// baseline (speedup 1.0000x reference)
#include <cuda_runtime.h>
#include <cuda_fp16.h>
#include <math.h>
#include <stdint.h>

#define N_SRC1 200000
#define N_TGT1 50000
#define N_TGT2 10000
#define E1 1000000
#define E2 300000
#define F_IN 256
#define F_HID 192
#define F_OUT 128

// ---------------- scratch ----------------
__device__ int g_zb[N_TGT1 + N_TGT2 + 2];
#define g_deg1 (g_zb)
#define g_deg2 (g_zb + N_TGT1)
#define g_ctr  (g_zb + N_TGT1 + N_TGT2)

__device__ int g_off1[N_TGT1 + 1];
__device__ int g_pos1[N_TGT1];
__device__ int g_idx1[E1];

__device__ int g_off2[N_TGT2 + 1];
__device__ int g_pos2[N_TGT2];
__device__ int g_idx2[E2];

__device__ int g_bsum1[256];
__device__ int g_bsum2[256];

__device__ __align__(16) __half g_xhi[(size_t)N_SRC1 * 256];

__device__ __align__(16) __half g_a1hi[(size_t)N_TGT1 * 256];
__device__ __align__(16) __half g_a1loA[(size_t)N_TGT1 * 256];
__device__ __align__(16) __half g_a1loB[(size_t)N_TGT1 * 256];
__device__ __align__(16) __half g_whi[(size_t)F_HID * 512];

__device__ __align__(16) __half g_a2hi[(size_t)N_TGT2 * 384];
__device__ __align__(16) __half g_a2lo[(size_t)N_TGT2 * 384];
__device__ __align__(16) __half g_w2hi[(size_t)F_HID * 384];
__device__ __align__(16) __half g_w2lo[(size_t)F_HID * 384];

__device__ __align__(16) __half g_a3hi[(size_t)N_TGT2 * 192];
__device__ __align__(16) __half g_a3lo[(size_t)N_TGT2 * 192];
__device__ __align__(16) __half g_w3hi[(size_t)F_HID * 192];
__device__ __align__(16) __half g_w3lo[(size_t)F_HID * 192];

__device__ __align__(16) __half g_a4hi[(size_t)N_TGT2 * 192];
__device__ __align__(16) __half g_a4lo[(size_t)N_TGT2 * 192];
__device__ __align__(16) __half g_w4hi[(size_t)F_OUT * 192];
__device__ __align__(16) __half g_w4lo[(size_t)F_OUT * 192];

__device__ __align__(16) __half g_h1h[(size_t)N_TGT1 * F_HID];

__device__ __forceinline__ void split1(float a, __half& h, __half& l) {
    h = __float2half_rn(a);
    l = __float2half_rn(a - __half2float(h));
}

union H8 { __half h[8]; uint4 u; };

// ============ launch 1 (fused): hist interleaved onto first HN threads + converts ============
#define XU (N_SRC1 * 32)
#define WQ 58368
#define HN ((E1 + E2) / 4)
__global__ void fused_pre_kernel(const float* __restrict__ x,
                                 const float* __restrict__ Wl1, const float* __restrict__ Wr1,
                                 const float* __restrict__ Wl2, const float* __restrict__ Wr2,
                                 const float* __restrict__ W1, const float* __restrict__ W2,
                                 const int* __restrict__ ei1, const int* __restrict__ ei2) {
    int i = blockIdx.x * blockDim.x + threadIdx.x;

    if (i < HN) {
        const int n1 = E1 / 4;
        if (i < n1) {
            int4 t = *(const int4*)(ei1 + E1 + i * 4);
            atomicAdd(&g_deg1[t.x], 1);
            atomicAdd(&g_deg1[t.y], 1);
            atomicAdd(&g_deg1[t.z], 1);
            atomicAdd(&g_deg1[t.w], 1);
        } else {
            int j = i - n1;
            int4 t = *(const int4*)(ei2 + E2 + j * 4);
            atomicAdd(&g_deg2[t.x], 1);
            atomicAdd(&g_deg2[t.y], 1);
            atomicAdd(&g_deg2[t.z], 1);
            atomicAdd(&g_deg2[t.w], 1);
        }
    }

    if (i < XU) {
        int r = i >> 5, c8 = (i & 31) << 3;
        const float4* xr = (const float4*)(x + (size_t)r * F_IN + c8);
        float4 va = xr[0], vb = xr[1];
        float f[8] = {va.x, va.y, va.z, va.w, vb.x, vb.y, vb.z, vb.w};
        H8 hi;
        #pragma unroll
        for (int j = 0; j < 8; j++) hi.h[j] = __float2half_rn(f[j]);
        *(uint4*)(g_xhi + (size_t)r * 256 + c8) = hi.u;
        if (r < N_TGT1) {
            H8 lo;
            #pragma unroll
            for (int j = 0; j < 8; j++)
                lo.h[j] = __float2half_rn(f[j] - __half2float(hi.h[j]));
            *(uint4*)(g_a1loB + (size_t)r * 256 + c8) = lo.u;
        }
        return;
    }
    int k = i - XU;
    if (k < WQ) {
        const float* in; __half* hi; __half* lo;
        int q, c4n, lda, col0;
        if (k < 12288)      { in = Wl1; hi = g_whi;  lo = (__half*)0; q = k;          c4n = 64; lda = 512; col0 = 0; }
        else if (k < 24576) { in = Wr1; hi = g_whi;  lo = (__half*)0; q = k - 12288;  c4n = 64; lda = 512; col0 = 256; }
        else if (k < 33792) { in = Wl2; hi = g_w2hi; lo = g_w2lo;     q = k - 24576;  c4n = 48; lda = 384; col0 = 0; }
        else if (k < 43008) { in = Wr2; hi = g_w2hi; lo = g_w2lo;     q = k - 33792;  c4n = 48; lda = 384; col0 = 192; }
        else if (k < 52224) { in = W1;  hi = g_w3hi; lo = g_w3lo;     q = k - 43008;  c4n = 48; lda = 192; col0 = 0; }
        else                { in = W2;  hi = g_w4hi; lo = g_w4lo;     q = k - 52224;  c4n = 48; lda = 192; col0 = 0; }
        int r = q / c4n, c = (q % c4n) << 2;
        float4 v = *(const float4*)(in + (size_t)r * (c4n * 4) + c);
        __half h0, h1, h2, h3, l0, l1, l2, l3;
        split1(v.x, h0, l0); split1(v.y, h1, l1);
        split1(v.z, h2, l2); split1(v.w, h3, l3);
        size_t o = (size_t)r * lda + col0 + c;
        *(__half2*)(hi + o)     = __halves2half2(h0, h1);
        *(__half2*)(hi + o + 2) = __halves2half2(h2, h3);
        if (lo) {
            *(__half2*)(lo + o)     = __halves2half2(l0, l1);
            *(__half2*)(lo + o + 2) = __halves2half2(l2, l3);
        }
    }
}

// ============ per-block scans; block base via atomic counter ============
__global__ void scan_block_both_kernel(int nb1) {
    const int* deg; int* off; int* pos; int* bsum; int n; int b; int list;
    if ((int)blockIdx.x < nb1) { deg = g_deg1; off = g_off1; pos = g_pos1; bsum = g_bsum1; n = N_TGT1; b = blockIdx.x; list = 0; }
    else { deg = g_deg2; off = g_off2; pos = g_pos2; bsum = g_bsum2; n = N_TGT2; b = blockIdx.x - nb1; list = 1; }
    __shared__ int wsum[16];
    int tid = threadIdx.x, lane = tid & 31, wid = tid >> 5;
    int i = b * 512 + tid;
    int v = (i < n) ? deg[i] : 0;
    int sc = v;
    #pragma unroll
    for (int o = 1; o < 32; o <<= 1) {
        int t = __shfl_up_sync(0xFFFFFFFFu, sc, o);
        if (lane >= o) sc += t;
    }
    if (lane == 31) wsum[wid] = sc;
    __syncthreads();
    if (wid == 0) {
        int ws = (lane < 16) ? wsum[lane] : 0;
        #pragma unroll
        for (int o = 1; o < 16; o <<= 1) {
            int t = __shfl_up_sync(0xFFFFFFFFu, ws, o);
            if (lane >= o) ws += t;
        }
        if (lane < 16) wsum[lane] = ws;
    }
    __syncthreads();
    int incl = sc + (wid ? wsum[wid - 1] : 0);
    if (i < n) { off[i + 1] = incl; pos[i] = incl - v; }
    if (tid == 511) {
        int base = atomicAdd(&g_ctr[list], incl);
        bsum[b] = base;
    }
}

// ============ fill CSR, 4 edges/thread ============
__global__ void fill_both_kernel(const int* __restrict__ ei1, const int* __restrict__ ei2) {
    int i = blockIdx.x * blockDim.x + threadIdx.x;
    const int n1 = E1 / 4, n2 = E2 / 4;
    if (i < n1) {
        int4 t = *(const int4*)(ei1 + E1 + i * 4);
        int4 s = *(const int4*)(ei1 + i * 4);
        int p0 = atomicAdd(&g_pos1[t.x], 1) + g_bsum1[t.x >> 9];
        int p1 = atomicAdd(&g_pos1[t.y], 1) + g_bsum1[t.y >> 9];
        int p2 = atomicAdd(&g_pos1[t.z], 1) + g_bsum1[t.z >> 9];
        int p3 = atomicAdd(&g_pos1[t.w], 1) + g_bsum1[t.w >> 9];
        g_idx1[p0] = s.x; g_idx1[p1] = s.y; g_idx1[p2] = s.z; g_idx1[p3] = s.w;
    } else if (i < n1 + n2) {
        int j = i - n1;
        int4 t = *(const int4*)(ei2 + E2 + j * 4);
        int4 s = *(const int4*)(ei2 + j * 4);
        int p0 = atomicAdd(&g_pos2[t.x], 1) + g_bsum2[t.x >> 9];
        int p1 = atomicAdd(&g_pos2[t.y], 1) + g_bsum2[t.y >> 9];
        int p2 = atomicAdd(&g_pos2[t.z], 1) + g_bsum2[t.z >> 9];
        int p3 = atomicAdd(&g_pos2[t.w], 1) + g_bsum2[t.w >> 9];
        g_idx2[p0] = s.x; g_idx2[p1] = s.y; g_idx2[p2] = s.z; g_idx2[p3] = s.w;
    }
}

__device__ __forceinline__ int seg_beg(const int* off, const int* bsum, int w) {
    return (w & 511) ? off[w] + bsum[w >> 9] : bsum[w >> 9];
}
__device__ __forceinline__ int seg_end(const int* off, const int* bsum, int w) {
    return off[w + 1] + bsum[w >> 9];
}

__device__ __forceinline__ void add8(float* a, uint4 v) {
    __half2* h = (__half2*)&v;
    float2 f0 = __half22float2(h[0]);
    float2 f1 = __half22float2(h[1]);
    float2 f2 = __half22float2(h[2]);
    float2 f3 = __half22float2(h[3]);
    a[0] += f0.x; a[1] += f0.y; a[2] += f1.x; a[3] += f1.y;
    a[4] += f2.x; a[5] += f2.y; a[6] += f3.x; a[7] += f3.y;
}

// ============ layer-1 segment mean ============
__global__ void agg1_kernel() {
    int w = (blockIdx.x * blockDim.x + threadIdx.x) >> 5;
    int lane = threadIdx.x & 31;
    if (w >= N_TGT1) return;
    int beg = seg_beg(g_off1, g_bsum1, w);
    int end = seg_end(g_off1, g_bsum1, w);
    const uint4* base = (const uint4*)g_xhi;
    float acc[8] = {0.f, 0.f, 0.f, 0.f, 0.f, 0.f, 0.f, 0.f};
    int e = beg;
    for (; e + 4 <= end; e += 4) {
        int i0 = g_idx1[e], i1 = g_idx1[e + 1], i2 = g_idx1[e + 2], i3 = g_idx1[e + 3];
        uint4 v0 = __ldg(base + (size_t)i0 * 32 + lane);
        uint4 v1 = __ldg(base + (size_t)i1 * 32 + lane);
        uint4 v2 = __ldg(base + (size_t)i2 * 32 + lane);
        uint4 v3 = __ldg(base + (size_t)i3 * 32 + lane);
        add8(acc, v0);
        add8(acc, v1);
        add8(acc, v2);
        add8(acc, v3);
    }
    for (; e < end; e++) {
        uint4 v = __ldg(base + (size_t)g_idx1[e] * 32 + lane);
        add8(acc, v);
    }
    int c = end - beg;
    float s = 1.0f / (float)(c > 1 ? c : 1);
    H8 hi, lo;
    #pragma unroll
    for (int j = 0; j < 8; j++) {
        float m = acc[j] * s;
        split1(m, hi.h[j], lo.h[j]);
    }
    size_t o = (size_t)w * 256 + lane * 8;
    *(uint4*)(g_a1hi + o)  = hi.u;
    *(uint4*)(g_a1loA + o) = lo.u;
}

// ============ layer-2 segment mean ============
__global__ void agg2_kernel() {
    int w = (blockIdx.x * blockDim.x + threadIdx.x) >> 5;
    int lane = threadIdx.x & 31;
    if (w >= N_TGT2) return;
    int beg = seg_beg(g_off2, g_bsum2, w);
    int end = seg_end(g_off2, g_bsum2, w);
    const uint4* base = (const uint4*)g_h1h;
    bool act = lane < 24;
    float acc[8] = {0.f, 0.f, 0.f, 0.f, 0.f, 0.f, 0.f, 0.f};
    int e = beg;
    for (; e + 2 <= end; e += 2) {
        int i0 = g_idx2[e], i1 = g_idx2[e + 1];
        if (act) {
            uint4 v0 = __ldg(base + (size_t)i0 * 24 + lane);
            uint4 v1 = __ldg(base + (size_t)i1 * 24 + lane);
            add8(acc, v0);
            add8(acc, v1);
        }
    }
    if (e < end && act) {
        uint4 v = __ldg(base + (size_t)g_idx2[e] * 24 + lane);
        add8(acc, v);
    }
    if (!act) return;
    int c = end - beg;
    float s = 1.0f / (float)(c > 1 ? c : 1);
    H8 hi, lo;
    #pragma unroll
    for (int j = 0; j < 8; j++) {
        float m = acc[j] * s;
        split1(m, hi.h[j], lo.h[j]);
    }
    size_t o = (size_t)w * 384 + lane * 8;
    *(uint4*)(g_a2hi + o) = hi.u;
    *(uint4*)(g_a2lo + o) = lo.u;
}

// ================= mma.sync fp16 split GEMM, 3-stage cp.async pipeline =================
#define ROWB 80

__device__ __forceinline__ uint32_t smem_u32(const void* p) {
    uint32_t a;
    asm("{ .reg .u64 t; cvta.to.shared.u64 t, %1; cvt.u32.u64 %0, t; }" : "=r"(a) : "l"(p));
    return a;
}
__device__ __forceinline__ void cp16(uint32_t s, const void* g) {
    asm volatile("cp.async.cg.shared.global [%0], [%1], 16;" :: "r"(s), "l"(g));
}
__device__ __forceinline__ void cp_commit() { asm volatile("cp.async.commit_group;"); }
template <int N>
__device__ __forceinline__ void cp_waitg() { asm volatile("cp.async.wait_group %0;" :: "n"(N)); }
__device__ __forceinline__ void ldm4(uint32_t* r, uint32_t a) {
    asm volatile("ldmatrix.sync.aligned.m8n8.x4.shared.b16 {%0,%1,%2,%3}, [%4];"
                 : "=r"(r[0]), "=r"(r[1]), "=r"(r[2]), "=r"(r[3]) : "r"(a));
}
__device__ __forceinline__ void mma_f16(float* c, const uint32_t* a, uint32_t b0, uint32_t b1) {
    asm volatile("mma.sync.aligned.m16n8k16.row.col.f32.f16.f16.f32 "
                 "{%0,%1,%2,%3},{%4,%5,%6,%7},{%8,%9},{%0,%1,%2,%3};"
                 : "+f"(c[0]), "+f"(c[1]), "+f"(c[2]), "+f"(c[3])
                 : "r"(a[0]), "r"(a[1]), "r"(a[2]), "r"(a[3]), "r"(b0), "r"(b1));
}

template <int NN, int TERMS, int KSPLIT>
__device__ __forceinline__ void gemm_mainloop(
    uint32_t smb, int tid, int w, int lane, int m0, int M, int K,
    const __half* ahi, const __half* alo,
    const __half* ahiB, const __half* aloB,
    const __half* whi, const __half* wlo,
    float acc[2][2 * (NN / 32)][4])
{
    constexpr int NJ = NN / 32;
    constexpr int NBI = (NN + 63) / 64;
    constexpr int SAHI = 0;
    constexpr int SALO = 128 * ROWB;
    constexpr int SBHI = 256 * ROWB;
    constexpr int SBLO = (256 + NN) * ROWB;
    constexpr int BUF = (256 + (TERMS == 3 ? 2 : 1) * NN) * ROWB;

    int wm = (w >> 1) * 32;
    int wn = (w & 1) * (NN / 2);
    int arow = tid >> 2;
    int aseg = (tid & 3) * 16;
    int asegk = (tid & 3) * 8;
    int chunks = K >> 5;

    auto load_chunk = [&](int c, int buf) {
        int k0 = c * 32;
        uint32_t base = smb + buf * BUF;
        const __half* Ah; const __half* Al; int alda, koff;
        if (KSPLIT) {
            if (k0 >= 256) { Ah = ahiB; Al = aloB; alda = 256; koff = k0 - 256; }
            else           { Ah = ahi;  Al = alo;  alda = 256; koff = k0; }
        } else { Ah = ahi; Al = alo; alda = K; koff = k0; }
        #pragma unroll
        for (int i = 0; i < 2; i++) {
            int row = arow + i * 64;
            int gr = m0 + row; if (gr >= M) gr = M - 1;
            size_t go = (size_t)gr * alda + koff + asegk;
            uint32_t so = row * ROWB + aseg;
            cp16(base + SAHI + so, Ah + go);
            cp16(base + SALO + so, Al + go);
        }
        #pragma unroll
        for (int i = 0; i < NBI; i++) {
            int row = arow + i * 64;
            if (row < NN) {
                size_t go = (size_t)row * K + k0 + asegk;
                uint32_t so = row * ROWB + aseg;
                cp16(base + SBHI + so, whi + go);
                if (TERMS == 3) cp16(base + SBLO + so, wlo + go);
            }
        }
    };

    int grp = lane >> 3, lr = lane & 7;
    int a_row_off = lr + (grp & 1) * 8;
    int a_k_off = (grp >> 1) * 8;
    int b_row_off = (grp & 2) * 4 + lr;
    int b_k_off = (grp & 1) * 8;

    // 3-stage prologue
    load_chunk(0, 0);
    cp_commit();
    if (chunks > 1) { load_chunk(1, 1); cp_commit(); }

    int buf = 0;
    #pragma unroll 1
    for (int c = 0; c < chunks; c++) {
        if (c + 2 < chunks) {
            int nb = (buf + 2) % 3;
            load_chunk(c + 2, nb);
            cp_commit();
            cp_waitg<2>();
        } else if (c + 1 < chunks) {
            cp_waitg<1>();
        } else {
            cp_waitg<0>();
        }
        __syncthreads();

        uint32_t base = smb + buf * BUF;
        #pragma unroll
        for (int s = 0; s < 2; s++) {
            uint32_t ah[2][4], al[2][4];
            #pragma unroll
            for (int mt = 0; mt < 2; mt++) {
                uint32_t ra = (wm + mt * 16 + a_row_off) * ROWB + (s * 16 + a_k_off) * 2;
                ldm4(ah[mt], base + SAHI + ra);
                ldm4(al[mt], base + SALO + ra);
            }
            #pragma unroll
            for (int j = 0; j < NJ; j++) {
                uint32_t rb = (wn + j * 16 + b_row_off) * ROWB + (s * 16 + b_k_off) * 2;
                uint32_t bh[4];
                ldm4(bh, base + SBHI + rb);
                #pragma unroll
                for (int mt = 0; mt < 2; mt++) {
                    mma_f16(acc[mt][2 * j],     ah[mt], bh[0], bh[1]);
                    mma_f16(acc[mt][2 * j],     al[mt], bh[0], bh[1]);
                    mma_f16(acc[mt][2 * j + 1], ah[mt], bh[2], bh[3]);
                    mma_f16(acc[mt][2 * j + 1], al[mt], bh[2], bh[3]);
                }
                if (TERMS == 3) {
                    uint32_t bl[4];
                    ldm4(bl, base + SBLO + rb);
                    #pragma unroll
                    for (int mt = 0; mt < 2; mt++) {
                        mma_f16(acc[mt][2 * j],     ah[mt], bl[0], bl[1]);
                        mma_f16(acc[mt][2 * j + 1], ah[mt], bl[2], bl[3]);
                    }
                }
            }
        }
        __syncthreads();
        buf = (buf + 1) % 3;
    }
}

template <int NN, int TERMS, int KSPLIT>
__global__ __launch_bounds__(256) void mmagemm_kernel(
    const __half* __restrict__ ahi, const __half* __restrict__ alo,
    const __half* __restrict__ ahiB, const __half* __restrict__ aloB,
    const __half* __restrict__ whi, const __half* __restrict__ wlo,
    const float* __restrict__ bias, int M, int K, int NTOT,
    float* __restrict__ Cf32, int relu_f32,
    __half* __restrict__ Ch16,
    __half* __restrict__ shi, __half* __restrict__ slo,
    int s_lda, int s_col0, int s_maxrow)
{
    extern __shared__ char sm[];
    uint32_t smb = smem_u32(sm);
    int tid = threadIdx.x;
    int w = tid >> 5, lane = tid & 31;
    int m0 = blockIdx.x * 128;
    int nb = blockIdx.y * NN;
    int wm = (w >> 1) * 32;
    int wn = (w & 1) * (NN / 2);

    const __half* whi_s = whi + (size_t)nb * K;
    const __half* wlo_s = wlo ? wlo + (size_t)nb * K : wlo;

    float acc[2][2 * (NN / 32)][4];
    #pragma unroll
    for (int i = 0; i < 2; i++)
        #pragma unroll
        for (int j = 0; j < 2 * (NN / 32); j++)
            #pragma unroll
            for (int k = 0; k < 4; k++) acc[i][j][k] = 0.f;

    gemm_mainloop<NN, TERMS, KSPLIT>(smb, tid, w, lane, m0, M, K, ahi, alo, ahiB, aloB, whi_s, wlo_s, acc);

    int g = lane >> 2, t = lane & 3;
    #pragma unroll
    for (int mt = 0; mt < 2; mt++) {
        int r0 = m0 + wm + mt * 16 + g;
        #pragma unroll
        for (int j = 0; j < 2 * (NN / 32); j++) {
            int col = nb + wn + j * 8 + 2 * t;
            float2 bv = *(const float2*)(bias + col);
            float o0 = acc[mt][j][0] + bv.x, o1 = acc[mt][j][1] + bv.y;
            float o2 = acc[mt][j][2] + bv.x, o3 = acc[mt][j][3] + bv.y;
            if (Cf32) {
                float p0 = o0, p1 = o1, p2 = o2, p3 = o3;
                if (relu_f32) {
                    p0 = fmaxf(p0, 0.f); p1 = fmaxf(p1, 0.f);
                    p2 = fmaxf(p2, 0.f); p3 = fmaxf(p3, 0.f);
                }
                if (r0 < M)     *(float2*)(Cf32 + (size_t)r0 * NTOT + col)       = make_float2(p0, p1);
                if (r0 + 8 < M) *(float2*)(Cf32 + (size_t)(r0 + 8) * NTOT + col) = make_float2(p2, p3);
            }
            if (Ch16) {
                float p0 = fmaxf(o0, 0.f), p1 = fmaxf(o1, 0.f);
                float p2 = fmaxf(o2, 0.f), p3 = fmaxf(o3, 0.f);
                if (r0 < M)
                    *(__half2*)(Ch16 + (size_t)r0 * NTOT + col) =
                        __halves2half2(__float2half_rn(p0), __float2half_rn(p1));
                if (r0 + 8 < M)
                    *(__half2*)(Ch16 + (size_t)(r0 + 8) * NTOT + col) =
                        __halves2half2(__float2half_rn(p2), __float2half_rn(p3));
            }
            if (shi) {
                o0 = fmaxf(o0, 0.f); o1 = fmaxf(o1, 0.f);
                o2 = fmaxf(o2, 0.f); o3 = fmaxf(o3, 0.f);
                __half h0, h1, h2, h3, l0, l1, l2, l3;
                split1(o0, h0, l0); split1(o1, h1, l1);
                split1(o2, h2, l2); split1(o3, h3, l3);
                if (r0 < s_maxrow) {
                    size_t o = (size_t)r0 * s_lda + s_col0 + col;
                    *(__half2*)(shi + o) = __halves2half2(h0, h1);
                    *(__half2*)(slo + o) = __halves2half2(l0, l1);
                }
                if (r0 + 8 < s_maxrow) {
                    size_t o = (size_t)(r0 + 8) * s_lda + s_col0 + col;
                    *(__half2*)(shi + o) = __halves2half2(h2, h3);
                    *(__half2*)(slo + o) = __halves2half2(l2, l3);
                }
            }
        }
    }
}

// ============ gemm (NN=128, TERMS=3) fused with log_softmax epilogue ============
__global__ __launch_bounds__(256) void gemm_softmax_kernel(
    const __half* __restrict__ ahi, const __half* __restrict__ alo,
    const __half* __restrict__ whi, const __half* __restrict__ wlo,
    const float* __restrict__ bias, int M, int K,
    float* __restrict__ out)
{
    extern __shared__ char sm[];
    uint32_t smb = smem_u32(sm);
    int tid = threadIdx.x;
    int w = tid >> 5, lane = tid & 31;
    int m0 = blockIdx.x * 128;
    int wm = (w >> 1) * 32;
    int wn = (w & 1) * 64;

    float acc[2][8][4];
    #pragma unroll
    for (int i = 0; i < 2; i++)
        #pragma unroll
        for (int j = 0; j < 8; j++)
            #pragma unroll
            for (int k = 0; k < 4; k++) acc[i][j][k] = 0.f;

    gemm_mainloop<128, 3, 0>(smb, tid, w, lane, m0, M, K, ahi, alo, ahi, alo, whi, wlo, acc);

    float* es = (float*)sm;
    int g = lane >> 2, t = lane & 3;
    #pragma unroll
    for (int mt = 0; mt < 2; mt++) {
        int r = wm + mt * 16 + g;
        #pragma unroll
        for (int j = 0; j < 8; j++) {
            int col = wn + j * 8 + 2 * t;
            float2 bv = *(const float2*)(bias + col);
            *(float2*)&es[(r)     * 132 + col] = make_float2(acc[mt][j][0] + bv.x, acc[mt][j][1] + bv.y);
            *(float2*)&es[(r + 8) * 132 + col] = make_float2(acc[mt][j][2] + bv.x, acc[mt][j][3] + bv.y);
        }
    }
    __syncthreads();

    for (int rr = 0; rr < 16; rr++) {
        int r = w * 16 + rr;
        int gr = m0 + r;
        if (gr >= M) break;
        float4 v = *(float4*)&es[r * 132 + lane * 4];
        float m = fmaxf(fmaxf(v.x, v.y), fmaxf(v.z, v.w));
        #pragma unroll
        for (int o = 16; o > 0; o >>= 1) m = fmaxf(m, __shfl_xor_sync(0xFFFFFFFFu, m, o));
        float s = expf(v.x - m) + expf(v.y - m) + expf(v.z - m) + expf(v.w - m);
        #pragma unroll
        for (int o = 16; o > 0; o >>= 1) s += __shfl_xor_sync(0xFFFFFFFFu, s, o);
        float l = m + logf(s);
        *(float4*)(out + (size_t)gr * F_OUT + lane * 4) =
            make_float4(v.x - l, v.y - l, v.z - l, v.w - l);
    }
}

// ---------------- launch ----------------
extern "C" void kernel_launch(void* const* d_in, const int* in_sizes, int n_in,
                              void* d_out, int out_size) {
    const float* x   = (const float*)d_in[0];
    const int*   ei1 = (const int*)d_in[1];
    const int*   ei2 = (const int*)d_in[2];
    const float* Wl1 = (const float*)d_in[3];
    const float* bl1 = (const float*)d_in[4];
    const float* Wr1 = (const float*)d_in[5];
    const float* Wl2 = (const float*)d_in[6];
    const float* bl2 = (const float*)d_in[7];
    const float* Wr2 = (const float*)d_in[8];
    const float* W1  = (const float*)d_in[9];
    const float* b1  = (const float*)d_in[10];
    const float* W2  = (const float*)d_in[11];
    const float* b2  = (const float*)d_in[12];

    float* out = (float*)d_out;
    float* out_ls  = out;
    float* out_emb = out + (size_t)N_TGT2 * F_OUT;

    int* zb;
    __half *xhi, *a1hi, *a1loA, *a1loB, *whi, *h1h;
    __half *a2hi, *a2lo, *w2hi, *w2lo;
    __half *a3hi, *a3lo, *w3hi, *w3lo;
    __half *a4hi, *a4lo, *w4hi, *w4lo;
    cudaGetSymbolAddress((void**)&zb, g_zb);
    cudaGetSymbolAddress((void**)&xhi, g_xhi);
    cudaGetSymbolAddress((void**)&a1hi, g_a1hi);
    cudaGetSymbolAddress((void**)&a1loA, g_a1loA);
    cudaGetSymbolAddress((void**)&a1loB, g_a1loB);
    cudaGetSymbolAddress((void**)&whi, g_whi);
    cudaGetSymbolAddress((void**)&h1h, g_h1h);
    cudaGetSymbolAddress((void**)&a2hi, g_a2hi);
    cudaGetSymbolAddress((void**)&a2lo, g_a2lo);
    cudaGetSymbolAddress((void**)&w2hi, g_w2hi);
    cudaGetSymbolAddress((void**)&w2lo, g_w2lo);
    cudaGetSymbolAddress((void**)&a3hi, g_a3hi);
    cudaGetSymbolAddress((void**)&a3lo, g_a3lo);
    cudaGetSymbolAddress((void**)&w3hi, g_w3hi);
    cudaGetSymbolAddress((void**)&w3lo, g_w3lo);
    cudaGetSymbolAddress((void**)&a4hi, g_a4hi);
    cudaGetSymbolAddress((void**)&a4lo, g_a4lo);
    cudaGetSymbolAddress((void**)&w4hi, g_w4hi);
    cudaGetSymbolAddress((void**)&w4lo, g_w4lo);

    const int SMEM192_2 = 3 * (256 + 192) * ROWB;     // 107520
    const int SMEM96_3  = 3 * (256 + 2 * 96) * ROWB;  // 107520
    const int SMEM128_3 = 3 * (256 + 2 * 128) * ROWB; // 122880
    cudaFuncSetAttribute((const void*)mmagemm_kernel<192, 2, 1>, cudaFuncAttributeMaxDynamicSharedMemorySize, SMEM192_2);
    cudaFuncSetAttribute((const void*)mmagemm_kernel<96, 3, 0>, cudaFuncAttributeMaxDynamicSharedMemorySize, SMEM96_3);
    cudaFuncSetAttribute((const void*)gemm_softmax_kernel, cudaFuncAttributeMaxDynamicSharedMemorySize, SMEM128_3);

    int nb1 = (N_TGT1 + 511) / 512;
    int nb2 = (N_TGT2 + 511) / 512;

    cudaMemsetAsync(zb, 0, (N_TGT1 + N_TGT2 + 2) * sizeof(int), 0);

    {
        int total = XU + WQ;
        fused_pre_kernel<<<(total + 255) / 256, 256>>>(x, Wl1, Wr1, Wl2, Wr2, W1, W2, ei1, ei2);
    }
    scan_block_both_kernel<<<nb1 + nb2, 512>>>(nb1);
    fill_both_kernel<<<((E1 + E2) / 4 + 255) / 256, 256>>>(ei1, ei2);

    agg1_kernel<<<(N_TGT1 * 32 + 255) / 256, 256>>>();

    mmagemm_kernel<192, 2, 1><<<dim3((N_TGT1 + 127) / 128, 1), 256, SMEM192_2>>>(
        a1hi, a1loA, xhi, a1loB, whi, (const __half*)0, bl1, N_TGT1, 512, 192,
        (float*)0, 0,
        h1h,
        a2hi, a2lo, 384, 192, N_TGT2);

    agg2_kernel<<<(N_TGT2 * 32 + 255) / 256, 256>>>();

    mmagemm_kernel<96, 3, 0><<<dim3((N_TGT2 + 127) / 128, 2), 256, SMEM96_3>>>(
        a2hi, a2lo, (const __half*)0, (const __half*)0, w2hi, w2lo, bl2, N_TGT2, 384, 192,
        (float*)0, 0,
        (__half*)0,
        a3hi, a3lo, 192, 0, N_TGT2);

    mmagemm_kernel<96, 3, 0><<<dim3((N_TGT2 + 127) / 128, 2), 256, SMEM96_3>>>(
        a3hi, a3lo, (const __half*)0, (const __half*)0, w3hi, w3lo, b1, N_TGT2, 192, 192,
        out_emb, 0,
        (__half*)0,
        a4hi, a4lo, 192, 0, N_TGT2);

    gemm_softmax_kernel<<<(N_TGT2 + 127) / 128, 256, SMEM128_3>>>(
        a4hi, a4lo, w4hi, w4lo, b2, N_TGT2, 192, out_ls);
}

// round 16
// speedup vs baseline: 1.1534x; 1.1534x over previous
#include <cuda_runtime.h>
#include <cuda_fp16.h>
#include <math.h>
#include <stdint.h>

#define N_SRC1 200000
#define N_TGT1 50000
#define N_TGT2 10000
#define E1 1000000
#define E2 300000
#define F_IN 256
#define F_HID 192
#define F_OUT 128

// ---------------- scratch ----------------
__device__ int g_zb[N_TGT1 + N_TGT2 + 2];
#define g_deg1 (g_zb)
#define g_deg2 (g_zb + N_TGT1)
#define g_ctr  (g_zb + N_TGT1 + N_TGT2)

__device__ int g_off1[N_TGT1 + 1];
__device__ int g_pos1[N_TGT1];
__device__ int g_idx1[E1];

__device__ int g_off2[N_TGT2 + 1];
__device__ int g_pos2[N_TGT2];
__device__ int g_idx2[E2];

__device__ int g_bsum1[256];
__device__ int g_bsum2[256];

__device__ __align__(16) __half g_xhi[(size_t)N_SRC1 * 256];

// layer-1 A: agg-hi only (K<256); x-hi half comes straight from g_xhi
__device__ __align__(16) __half g_a1hi[(size_t)N_TGT1 * 256];
__device__ __align__(16) __half g_whi[(size_t)F_HID * 512];

__device__ __align__(16) __half g_a2hi[(size_t)N_TGT2 * 384];
__device__ __align__(16) __half g_a2lo[(size_t)N_TGT2 * 384];
__device__ __align__(16) __half g_w2hi[(size_t)F_HID * 384];
__device__ __align__(16) __half g_w2lo[(size_t)F_HID * 384];

__device__ __align__(16) __half g_a3hi[(size_t)N_TGT2 * 192];
__device__ __align__(16) __half g_a3lo[(size_t)N_TGT2 * 192];
__device__ __align__(16) __half g_w3hi[(size_t)F_HID * 192];
__device__ __align__(16) __half g_w3lo[(size_t)F_HID * 192];

__device__ __align__(16) __half g_a4hi[(size_t)N_TGT2 * 192];
__device__ __align__(16) __half g_a4lo[(size_t)N_TGT2 * 192];
__device__ __align__(16) __half g_w4hi[(size_t)F_OUT * 192];
__device__ __align__(16) __half g_w4lo[(size_t)F_OUT * 192];

__device__ __align__(16) __half g_h1h[(size_t)N_TGT1 * F_HID];

__device__ __forceinline__ void split1(float a, __half& h, __half& l) {
    h = __float2half_rn(a);
    l = __float2half_rn(a - __half2float(h));
}

union H8 { __half h[8]; uint4 u; };

// ============ launch 1 (fused): hist interleaved + converts (x-hi only now) ============
#define XU (N_SRC1 * 32)
#define WQ 58368
#define HN ((E1 + E2) / 4)
__global__ void fused_pre_kernel(const float* __restrict__ x,
                                 const float* __restrict__ Wl1, const float* __restrict__ Wr1,
                                 const float* __restrict__ Wl2, const float* __restrict__ Wr2,
                                 const float* __restrict__ W1, const float* __restrict__ W2,
                                 const int* __restrict__ ei1, const int* __restrict__ ei2) {
    int i = blockIdx.x * blockDim.x + threadIdx.x;

    if (i < HN) {
        const int n1 = E1 / 4;
        if (i < n1) {
            int4 t = *(const int4*)(ei1 + E1 + i * 4);
            atomicAdd(&g_deg1[t.x], 1);
            atomicAdd(&g_deg1[t.y], 1);
            atomicAdd(&g_deg1[t.z], 1);
            atomicAdd(&g_deg1[t.w], 1);
        } else {
            int j = i - n1;
            int4 t = *(const int4*)(ei2 + E2 + j * 4);
            atomicAdd(&g_deg2[t.x], 1);
            atomicAdd(&g_deg2[t.y], 1);
            atomicAdd(&g_deg2[t.z], 1);
            atomicAdd(&g_deg2[t.w], 1);
        }
    }

    if (i < XU) {
        int r = i >> 5, c8 = (i & 31) << 3;
        const float4* xr = (const float4*)(x + (size_t)r * F_IN + c8);
        float4 va = xr[0], vb = xr[1];
        float f[8] = {va.x, va.y, va.z, va.w, vb.x, vb.y, vb.z, vb.w};
        H8 hi;
        #pragma unroll
        for (int j = 0; j < 8; j++) hi.h[j] = __float2half_rn(f[j]);
        *(uint4*)(g_xhi + (size_t)r * 256 + c8) = hi.u;
        return;
    }
    int k = i - XU;
    if (k < WQ) {
        const float* in; __half* hi; __half* lo;
        int q, c4n, lda, col0;
        if (k < 12288)      { in = Wl1; hi = g_whi;  lo = (__half*)0; q = k;          c4n = 64; lda = 512; col0 = 0; }
        else if (k < 24576) { in = Wr1; hi = g_whi;  lo = (__half*)0; q = k - 12288;  c4n = 64; lda = 512; col0 = 256; }
        else if (k < 33792) { in = Wl2; hi = g_w2hi; lo = g_w2lo;     q = k - 24576;  c4n = 48; lda = 384; col0 = 0; }
        else if (k < 43008) { in = Wr2; hi = g_w2hi; lo = g_w2lo;     q = k - 33792;  c4n = 48; lda = 384; col0 = 192; }
        else if (k < 52224) { in = W1;  hi = g_w3hi; lo = g_w3lo;     q = k - 43008;  c4n = 48; lda = 192; col0 = 0; }
        else                { in = W2;  hi = g_w4hi; lo = g_w4lo;     q = k - 52224;  c4n = 48; lda = 192; col0 = 0; }
        int r = q / c4n, c = (q % c4n) << 2;
        float4 v = *(const float4*)(in + (size_t)r * (c4n * 4) + c);
        __half h0, h1, h2, h3, l0, l1, l2, l3;
        split1(v.x, h0, l0); split1(v.y, h1, l1);
        split1(v.z, h2, l2); split1(v.w, h3, l3);
        size_t o = (size_t)r * lda + col0 + c;
        *(__half2*)(hi + o)     = __halves2half2(h0, h1);
        *(__half2*)(hi + o + 2) = __halves2half2(h2, h3);
        if (lo) {
            *(__half2*)(lo + o)     = __halves2half2(l0, l1);
            *(__half2*)(lo + o + 2) = __halves2half2(l2, l3);
        }
    }
}

// ============ per-block scans; block base via atomic counter ============
__global__ void scan_block_both_kernel(int nb1) {
    const int* deg; int* off; int* pos; int* bsum; int n; int b; int list;
    if ((int)blockIdx.x < nb1) { deg = g_deg1; off = g_off1; pos = g_pos1; bsum = g_bsum1; n = N_TGT1; b = blockIdx.x; list = 0; }
    else { deg = g_deg2; off = g_off2; pos = g_pos2; bsum = g_bsum2; n = N_TGT2; b = blockIdx.x - nb1; list = 1; }
    __shared__ int wsum[16];
    int tid = threadIdx.x, lane = tid & 31, wid = tid >> 5;
    int i = b * 512 + tid;
    int v = (i < n) ? deg[i] : 0;
    int sc = v;
    #pragma unroll
    for (int o = 1; o < 32; o <<= 1) {
        int t = __shfl_up_sync(0xFFFFFFFFu, sc, o);
        if (lane >= o) sc += t;
    }
    if (lane == 31) wsum[wid] = sc;
    __syncthreads();
    if (wid == 0) {
        int ws = (lane < 16) ? wsum[lane] : 0;
        #pragma unroll
        for (int o = 1; o < 16; o <<= 1) {
            int t = __shfl_up_sync(0xFFFFFFFFu, ws, o);
            if (lane >= o) ws += t;
        }
        if (lane < 16) wsum[lane] = ws;
    }
    __syncthreads();
    int incl = sc + (wid ? wsum[wid - 1] : 0);
    if (i < n) { off[i + 1] = incl; pos[i] = incl - v; }
    if (tid == 511) {
        int base = atomicAdd(&g_ctr[list], incl);
        bsum[b] = base;
    }
}

// ============ fill CSR, 4 edges/thread ============
__global__ void fill_both_kernel(const int* __restrict__ ei1, const int* __restrict__ ei2) {
    int i = blockIdx.x * blockDim.x + threadIdx.x;
    const int n1 = E1 / 4, n2 = E2 / 4;
    if (i < n1) {
        int4 t = *(const int4*)(ei1 + E1 + i * 4);
        int4 s = *(const int4*)(ei1 + i * 4);
        int p0 = atomicAdd(&g_pos1[t.x], 1) + g_bsum1[t.x >> 9];
        int p1 = atomicAdd(&g_pos1[t.y], 1) + g_bsum1[t.y >> 9];
        int p2 = atomicAdd(&g_pos1[t.z], 1) + g_bsum1[t.z >> 9];
        int p3 = atomicAdd(&g_pos1[t.w], 1) + g_bsum1[t.w >> 9];
        g_idx1[p0] = s.x; g_idx1[p1] = s.y; g_idx1[p2] = s.z; g_idx1[p3] = s.w;
    } else if (i < n1 + n2) {
        int j = i - n1;
        int4 t = *(const int4*)(ei2 + E2 + j * 4);
        int4 s = *(const int4*)(ei2 + j * 4);
        int p0 = atomicAdd(&g_pos2[t.x], 1) + g_bsum2[t.x >> 9];
        int p1 = atomicAdd(&g_pos2[t.y], 1) + g_bsum2[t.y >> 9];
        int p2 = atomicAdd(&g_pos2[t.z], 1) + g_bsum2[t.z >> 9];
        int p3 = atomicAdd(&g_pos2[t.w], 1) + g_bsum2[t.w >> 9];
        g_idx2[p0] = s.x; g_idx2[p1] = s.y; g_idx2[p2] = s.z; g_idx2[p3] = s.w;
    }
}

__device__ __forceinline__ int seg_beg(const int* off, const int* bsum, int w) {
    return (w & 511) ? off[w] + bsum[w >> 9] : bsum[w >> 9];
}
__device__ __forceinline__ int seg_end(const int* off, const int* bsum, int w) {
    return off[w + 1] + bsum[w >> 9];
}

__device__ __forceinline__ void add8(float* a, uint4 v) {
    __half2* h = (__half2*)&v;
    float2 f0 = __half22float2(h[0]);
    float2 f1 = __half22float2(h[1]);
    float2 f2 = __half22float2(h[2]);
    float2 f3 = __half22float2(h[3]);
    a[0] += f0.x; a[1] += f0.y; a[2] += f1.x; a[3] += f1.y;
    a[4] += f2.x; a[5] += f2.y; a[6] += f3.x; a[7] += f3.y;
}

// ============ layer-1 segment mean: hi-only output ============
__global__ void agg1_kernel() {
    int w = (blockIdx.x * blockDim.x + threadIdx.x) >> 5;
    int lane = threadIdx.x & 31;
    if (w >= N_TGT1) return;
    int beg = seg_beg(g_off1, g_bsum1, w);
    int end = seg_end(g_off1, g_bsum1, w);
    const uint4* base = (const uint4*)g_xhi;
    float acc[8] = {0.f, 0.f, 0.f, 0.f, 0.f, 0.f, 0.f, 0.f};
    int e = beg;
    for (; e + 4 <= end; e += 4) {
        int i0 = g_idx1[e], i1 = g_idx1[e + 1], i2 = g_idx1[e + 2], i3 = g_idx1[e + 3];
        uint4 v0 = __ldg(base + (size_t)i0 * 32 + lane);
        uint4 v1 = __ldg(base + (size_t)i1 * 32 + lane);
        uint4 v2 = __ldg(base + (size_t)i2 * 32 + lane);
        uint4 v3 = __ldg(base + (size_t)i3 * 32 + lane);
        add8(acc, v0);
        add8(acc, v1);
        add8(acc, v2);
        add8(acc, v3);
    }
    for (; e < end; e++) {
        uint4 v = __ldg(base + (size_t)g_idx1[e] * 32 + lane);
        add8(acc, v);
    }
    int c = end - beg;
    float s = 1.0f / (float)(c > 1 ? c : 1);
    H8 hi;
    #pragma unroll
    for (int j = 0; j < 8; j++) hi.h[j] = __float2half_rn(acc[j] * s);
    *(uint4*)(g_a1hi + (size_t)w * 256 + lane * 8) = hi.u;
}

// ============ layer-2 segment mean ============
__global__ void agg2_kernel() {
    int w = (blockIdx.x * blockDim.x + threadIdx.x) >> 5;
    int lane = threadIdx.x & 31;
    if (w >= N_TGT2) return;
    int beg = seg_beg(g_off2, g_bsum2, w);
    int end = seg_end(g_off2, g_bsum2, w);
    const uint4* base = (const uint4*)g_h1h;
    bool act = lane < 24;
    float acc[8] = {0.f, 0.f, 0.f, 0.f, 0.f, 0.f, 0.f, 0.f};
    int e = beg;
    for (; e + 2 <= end; e += 2) {
        int i0 = g_idx2[e], i1 = g_idx2[e + 1];
        if (act) {
            uint4 v0 = __ldg(base + (size_t)i0 * 24 + lane);
            uint4 v1 = __ldg(base + (size_t)i1 * 24 + lane);
            add8(acc, v0);
            add8(acc, v1);
        }
    }
    if (e < end && act) {
        uint4 v = __ldg(base + (size_t)g_idx2[e] * 24 + lane);
        add8(acc, v);
    }
    if (!act) return;
    int c = end - beg;
    float s = 1.0f / (float)(c > 1 ? c : 1);
    H8 hi, lo;
    #pragma unroll
    for (int j = 0; j < 8; j++) {
        float m = acc[j] * s;
        split1(m, hi.h[j], lo.h[j]);
    }
    size_t o = (size_t)w * 384 + lane * 8;
    *(uint4*)(g_a2hi + o) = hi.u;
    *(uint4*)(g_a2lo + o) = lo.u;
}

// ================= mma.sync fp16 GEMM, 3-stage pipeline =================
// TERMS: 1 = A-hi x W-hi ; 3 = (Ahi+Alo) x Whi + Ahi x Wlo
#define ROWB 80

__device__ __forceinline__ uint32_t smem_u32(const void* p) {
    uint32_t a;
    asm("{ .reg .u64 t; cvta.to.shared.u64 t, %1; cvt.u32.u64 %0, t; }" : "=r"(a) : "l"(p));
    return a;
}
__device__ __forceinline__ void cp16(uint32_t s, const void* g) {
    asm volatile("cp.async.cg.shared.global [%0], [%1], 16;" :: "r"(s), "l"(g));
}
__device__ __forceinline__ void cp_commit() { asm volatile("cp.async.commit_group;"); }
template <int N>
__device__ __forceinline__ void cp_waitg() { asm volatile("cp.async.wait_group %0;" :: "n"(N)); }
__device__ __forceinline__ void ldm4(uint32_t* r, uint32_t a) {
    asm volatile("ldmatrix.sync.aligned.m8n8.x4.shared.b16 {%0,%1,%2,%3}, [%4];"
                 : "=r"(r[0]), "=r"(r[1]), "=r"(r[2]), "=r"(r[3]) : "r"(a));
}
__device__ __forceinline__ void mma_f16(float* c, const uint32_t* a, uint32_t b0, uint32_t b1) {
    asm volatile("mma.sync.aligned.m16n8k16.row.col.f32.f16.f16.f32 "
                 "{%0,%1,%2,%3},{%4,%5,%6,%7},{%8,%9},{%0,%1,%2,%3};"
                 : "+f"(c[0]), "+f"(c[1]), "+f"(c[2]), "+f"(c[3])
                 : "r"(a[0]), "r"(a[1]), "r"(a[2]), "r"(a[3]), "r"(b0), "r"(b1));
}

template <int NN, int TERMS, int KSPLIT>
__device__ __forceinline__ void gemm_mainloop(
    uint32_t smb, int tid, int w, int lane, int m0, int M, int K,
    const __half* ahi, const __half* alo,
    const __half* ahiB, const __half* aloB,
    const __half* whi, const __half* wlo,
    float acc[2][2 * (NN / 32)][4])
{
    constexpr int NJ = NN / 32;
    constexpr int NBI = (NN + 63) / 64;
    constexpr int AR = (TERMS >= 2) ? 256 : 128;   // A smem rows (hi [+lo])
    constexpr int SAHI = 0;
    constexpr int SALO = 128 * ROWB;               // valid only when TERMS>=2
    constexpr int SBHI = AR * ROWB;
    constexpr int SBLO = (AR + NN) * ROWB;
    constexpr int BUF = (AR + (TERMS == 3 ? 2 : 1) * NN) * ROWB;

    int wm = (w >> 1) * 32;
    int wn = (w & 1) * (NN / 2);
    int arow = tid >> 2;
    int aseg = (tid & 3) * 16;
    int asegk = (tid & 3) * 8;
    int chunks = K >> 5;

    auto load_chunk = [&](int c, int buf) {
        int k0 = c * 32;
        uint32_t base = smb + buf * BUF;
        const __half* Ah; const __half* Al; int alda, koff;
        if (KSPLIT) {
            if (k0 >= 256) { Ah = ahiB; Al = aloB; alda = 256; koff = k0 - 256; }
            else           { Ah = ahi;  Al = alo;  alda = 256; koff = k0; }
        } else { Ah = ahi; Al = alo; alda = K; koff = k0; }
        #pragma unroll
        for (int i = 0; i < 2; i++) {
            int row = arow + i * 64;
            int gr = m0 + row; if (gr >= M) gr = M - 1;
            size_t go = (size_t)gr * alda + koff + asegk;
            uint32_t so = row * ROWB + aseg;
            cp16(base + SAHI + so, Ah + go);
            if (TERMS >= 2) cp16(base + SALO + so, Al + go);
        }
        #pragma unroll
        for (int i = 0; i < NBI; i++) {
            int row = arow + i * 64;
            if (row < NN) {
                size_t go = (size_t)row * K + k0 + asegk;
                uint32_t so = row * ROWB + aseg;
                cp16(base + SBHI + so, whi + go);
                if (TERMS == 3) cp16(base + SBLO + so, wlo + go);
            }
        }
    };

    int grp = lane >> 3, lr = lane & 7;
    int a_row_off = lr + (grp & 1) * 8;
    int a_k_off = (grp >> 1) * 8;
    int b_row_off = (grp & 2) * 4 + lr;
    int b_k_off = (grp & 1) * 8;

    load_chunk(0, 0);
    cp_commit();
    if (chunks > 1) { load_chunk(1, 1); cp_commit(); }

    int buf = 0;
    #pragma unroll 1
    for (int c = 0; c < chunks; c++) {
        if (c + 2 < chunks) {
            int nb = (buf + 2) % 3;
            load_chunk(c + 2, nb);
            cp_commit();
            cp_waitg<2>();
        } else if (c + 1 < chunks) {
            cp_waitg<1>();
        } else {
            cp_waitg<0>();
        }
        __syncthreads();

        uint32_t base = smb + buf * BUF;
        #pragma unroll
        for (int s = 0; s < 2; s++) {
            uint32_t ah[2][4], al[2][4];
            #pragma unroll
            for (int mt = 0; mt < 2; mt++) {
                uint32_t ra = (wm + mt * 16 + a_row_off) * ROWB + (s * 16 + a_k_off) * 2;
                ldm4(ah[mt], base + SAHI + ra);
                if (TERMS >= 2) ldm4(al[mt], base + SALO + ra);
            }
            #pragma unroll
            for (int j = 0; j < NJ; j++) {
                uint32_t rb = (wn + j * 16 + b_row_off) * ROWB + (s * 16 + b_k_off) * 2;
                uint32_t bh[4];
                ldm4(bh, base + SBHI + rb);
                #pragma unroll
                for (int mt = 0; mt < 2; mt++) {
                    mma_f16(acc[mt][2 * j],     ah[mt], bh[0], bh[1]);
                    mma_f16(acc[mt][2 * j + 1], ah[mt], bh[2], bh[3]);
                    if (TERMS >= 2) {
                        mma_f16(acc[mt][2 * j],     al[mt], bh[0], bh[1]);
                        mma_f16(acc[mt][2 * j + 1], al[mt], bh[2], bh[3]);
                    }
                }
                if (TERMS == 3) {
                    uint32_t bl[4];
                    ldm4(bl, base + SBLO + rb);
                    #pragma unroll
                    for (int mt = 0; mt < 2; mt++) {
                        mma_f16(acc[mt][2 * j],     ah[mt], bl[0], bl[1]);
                        mma_f16(acc[mt][2 * j + 1], ah[mt], bl[2], bl[3]);
                    }
                }
            }
        }
        __syncthreads();
        buf = (buf + 1) % 3;
    }
}

template <int NN, int TERMS, int KSPLIT>
__global__ __launch_bounds__(256) void mmagemm_kernel(
    const __half* __restrict__ ahi, const __half* __restrict__ alo,
    const __half* __restrict__ ahiB, const __half* __restrict__ aloB,
    const __half* __restrict__ whi, const __half* __restrict__ wlo,
    const float* __restrict__ bias, int M, int K, int NTOT,
    float* __restrict__ Cf32, int relu_f32,
    __half* __restrict__ Ch16,
    __half* __restrict__ shi, __half* __restrict__ slo,
    int s_lda, int s_col0, int s_maxrow)
{
    extern __shared__ char sm[];
    uint32_t smb = smem_u32(sm);
    int tid = threadIdx.x;
    int w = tid >> 5, lane = tid & 31;
    int m0 = blockIdx.x * 128;
    int nb = blockIdx.y * NN;
    int wm = (w >> 1) * 32;
    int wn = (w & 1) * (NN / 2);

    const __half* whi_s = whi + (size_t)nb * K;
    const __half* wlo_s = wlo ? wlo + (size_t)nb * K : wlo;

    float acc[2][2 * (NN / 32)][4];
    #pragma unroll
    for (int i = 0; i < 2; i++)
        #pragma unroll
        for (int j = 0; j < 2 * (NN / 32); j++)
            #pragma unroll
            for (int k = 0; k < 4; k++) acc[i][j][k] = 0.f;

    gemm_mainloop<NN, TERMS, KSPLIT>(smb, tid, w, lane, m0, M, K, ahi, alo, ahiB, aloB, whi_s, wlo_s, acc);

    int g = lane >> 2, t = lane & 3;
    #pragma unroll
    for (int mt = 0; mt < 2; mt++) {
        int r0 = m0 + wm + mt * 16 + g;
        #pragma unroll
        for (int j = 0; j < 2 * (NN / 32); j++) {
            int col = nb + wn + j * 8 + 2 * t;
            float2 bv = *(const float2*)(bias + col);
            float o0 = acc[mt][j][0] + bv.x, o1 = acc[mt][j][1] + bv.y;
            float o2 = acc[mt][j][2] + bv.x, o3 = acc[mt][j][3] + bv.y;
            if (Cf32) {
                float p0 = o0, p1 = o1, p2 = o2, p3 = o3;
                if (relu_f32) {
                    p0 = fmaxf(p0, 0.f); p1 = fmaxf(p1, 0.f);
                    p2 = fmaxf(p2, 0.f); p3 = fmaxf(p3, 0.f);
                }
                if (r0 < M)     *(float2*)(Cf32 + (size_t)r0 * NTOT + col)       = make_float2(p0, p1);
                if (r0 + 8 < M) *(float2*)(Cf32 + (size_t)(r0 + 8) * NTOT + col) = make_float2(p2, p3);
            }
            if (Ch16) {
                float p0 = fmaxf(o0, 0.f), p1 = fmaxf(o1, 0.f);
                float p2 = fmaxf(o2, 0.f), p3 = fmaxf(o3, 0.f);
                if (r0 < M)
                    *(__half2*)(Ch16 + (size_t)r0 * NTOT + col) =
                        __halves2half2(__float2half_rn(p0), __float2half_rn(p1));
                if (r0 + 8 < M)
                    *(__half2*)(Ch16 + (size_t)(r0 + 8) * NTOT + col) =
                        __halves2half2(__float2half_rn(p2), __float2half_rn(p3));
            }
            if (shi) {
                o0 = fmaxf(o0, 0.f); o1 = fmaxf(o1, 0.f);
                o2 = fmaxf(o2, 0.f); o3 = fmaxf(o3, 0.f);
                __half h0, h1, h2, h3, l0, l1, l2, l3;
                split1(o0, h0, l0); split1(o1, h1, l1);
                split1(o2, h2, l2); split1(o3, h3, l3);
                if (r0 < s_maxrow) {
                    size_t o = (size_t)r0 * s_lda + s_col0 + col;
                    *(__half2*)(shi + o) = __halves2half2(h0, h1);
                    *(__half2*)(slo + o) = __halves2half2(l0, l1);
                }
                if (r0 + 8 < s_maxrow) {
                    size_t o = (size_t)(r0 + 8) * s_lda + s_col0 + col;
                    *(__half2*)(shi + o) = __halves2half2(h2, h3);
                    *(__half2*)(slo + o) = __halves2half2(l2, l3);
                }
            }
        }
    }
}

// ============ gemm (NN=128, TERMS=3) fused with log_softmax epilogue ============
__global__ __launch_bounds__(256) void gemm_softmax_kernel(
    const __half* __restrict__ ahi, const __half* __restrict__ alo,
    const __half* __restrict__ whi, const __half* __restrict__ wlo,
    const float* __restrict__ bias, int M, int K,
    float* __restrict__ out)
{
    extern __shared__ char sm[];
    uint32_t smb = smem_u32(sm);
    int tid = threadIdx.x;
    int w = tid >> 5, lane = tid & 31;
    int m0 = blockIdx.x * 128;
    int wm = (w >> 1) * 32;
    int wn = (w & 1) * 64;

    float acc[2][8][4];
    #pragma unroll
    for (int i = 0; i < 2; i++)
        #pragma unroll
        for (int j = 0; j < 8; j++)
            #pragma unroll
            for (int k = 0; k < 4; k++) acc[i][j][k] = 0.f;

    gemm_mainloop<128, 3, 0>(smb, tid, w, lane, m0, M, K, ahi, alo, ahi, alo, whi, wlo, acc);

    float* es = (float*)sm;
    int g = lane >> 2, t = lane & 3;
    #pragma unroll
    for (int mt = 0; mt < 2; mt++) {
        int r = wm + mt * 16 + g;
        #pragma unroll
        for (int j = 0; j < 8; j++) {
            int col = wn + j * 8 + 2 * t;
            float2 bv = *(const float2*)(bias + col);
            *(float2*)&es[(r)     * 132 + col] = make_float2(acc[mt][j][0] + bv.x, acc[mt][j][1] + bv.y);
            *(float2*)&es[(r + 8) * 132 + col] = make_float2(acc[mt][j][2] + bv.x, acc[mt][j][3] + bv.y);
        }
    }
    __syncthreads();

    for (int rr = 0; rr < 16; rr++) {
        int r = w * 16 + rr;
        int gr = m0 + r;
        if (gr >= M) break;
        float4 v = *(float4*)&es[r * 132 + lane * 4];
        float m = fmaxf(fmaxf(v.x, v.y), fmaxf(v.z, v.w));
        #pragma unroll
        for (int o = 16; o > 0; o >>= 1) m = fmaxf(m, __shfl_xor_sync(0xFFFFFFFFu, m, o));
        float s = expf(v.x - m) + expf(v.y - m) + expf(v.z - m) + expf(v.w - m);
        #pragma unroll
        for (int o = 16; o > 0; o >>= 1) s += __shfl_xor_sync(0xFFFFFFFFu, s, o);
        float l = m + logf(s);
        *(float4*)(out + (size_t)gr * F_OUT + lane * 4) =
            make_float4(v.x - l, v.y - l, v.z - l, v.w - l);
    }
}

// ---------------- launch ----------------
extern "C" void kernel_launch(void* const* d_in, const int* in_sizes, int n_in,
                              void* d_out, int out_size) {
    const float* x   = (const float*)d_in[0];
    const int*   ei1 = (const int*)d_in[1];
    const int*   ei2 = (const int*)d_in[2];
    const float* Wl1 = (const float*)d_in[3];
    const float* bl1 = (const float*)d_in[4];
    const float* Wr1 = (const float*)d_in[5];
    const float* Wl2 = (const float*)d_in[6];
    const float* bl2 = (const float*)d_in[7];
    const float* Wr2 = (const float*)d_in[8];
    const float* W1  = (const float*)d_in[9];
    const float* b1  = (const float*)d_in[10];
    const float* W2  = (const float*)d_in[11];
    const float* b2  = (const float*)d_in[12];

    float* out = (float*)d_out;
    float* out_ls  = out;
    float* out_emb = out + (size_t)N_TGT2 * F_OUT;

    int* zb;
    __half *xhi, *a1hi, *whi, *h1h;
    __half *a2hi, *a2lo, *w2hi, *w2lo;
    __half *a3hi, *a3lo, *w3hi, *w3lo;
    __half *a4hi, *a4lo, *w4hi, *w4lo;
    cudaGetSymbolAddress((void**)&zb, g_zb);
    cudaGetSymbolAddress((void**)&xhi, g_xhi);
    cudaGetSymbolAddress((void**)&a1hi, g_a1hi);
    cudaGetSymbolAddress((void**)&whi, g_whi);
    cudaGetSymbolAddress((void**)&h1h, g_h1h);
    cudaGetSymbolAddress((void**)&a2hi, g_a2hi);
    cudaGetSymbolAddress((void**)&a2lo, g_a2lo);
    cudaGetSymbolAddress((void**)&w2hi, g_w2hi);
    cudaGetSymbolAddress((void**)&w2lo, g_w2lo);
    cudaGetSymbolAddress((void**)&a3hi, g_a3hi);
    cudaGetSymbolAddress((void**)&a3lo, g_a3lo);
    cudaGetSymbolAddress((void**)&w3hi, g_w3hi);
    cudaGetSymbolAddress((void**)&w3lo, g_w3lo);
    cudaGetSymbolAddress((void**)&a4hi, g_a4hi);
    cudaGetSymbolAddress((void**)&a4lo, g_a4lo);
    cudaGetSymbolAddress((void**)&w4hi, g_w4hi);
    cudaGetSymbolAddress((void**)&w4lo, g_w4lo);

    const int SMEM192_1 = 3 * (128 + 192) * ROWB;     // 76800
    const int SMEM96_3  = 3 * (256 + 2 * 96) * ROWB;  // 107520
    const int SMEM128_3 = 3 * (256 + 2 * 128) * ROWB; // 122880
    cudaFuncSetAttribute((const void*)mmagemm_kernel<192, 1, 1>, cudaFuncAttributeMaxDynamicSharedMemorySize, SMEM192_1);
    cudaFuncSetAttribute((const void*)mmagemm_kernel<96, 3, 0>, cudaFuncAttributeMaxDynamicSharedMemorySize, SMEM96_3);
    cudaFuncSetAttribute((const void*)gemm_softmax_kernel, cudaFuncAttributeMaxDynamicSharedMemorySize, SMEM128_3);

    int nb1 = (N_TGT1 + 511) / 512;
    int nb2 = (N_TGT2 + 511) / 512;

    cudaMemsetAsync(zb, 0, (N_TGT1 + N_TGT2 + 2) * sizeof(int), 0);

    {
        int total = XU + WQ;
        fused_pre_kernel<<<(total + 255) / 256, 256>>>(x, Wl1, Wr1, Wl2, Wr2, W1, W2, ei1, ei2);
    }
    scan_block_both_kernel<<<nb1 + nb2, 512>>>(nb1);
    fill_both_kernel<<<((E1 + E2) / 4 + 255) / 256, 256>>>(ei1, ei2);

    agg1_kernel<<<(N_TGT1 * 32 + 255) / 256, 256>>>();

    // layer-1 GEMM (1-term pure fp16, split-A: agg-hi | x-hi)
    mmagemm_kernel<192, 1, 1><<<dim3((N_TGT1 + 127) / 128, 1), 256, SMEM192_1>>>(
        a1hi, (const __half*)0, xhi, (const __half*)0, whi, (const __half*)0,
        bl1, N_TGT1, 512, 192,
        (float*)0, 0,
        h1h,
        a2hi, a2lo, 384, 192, N_TGT2);

    agg2_kernel<<<(N_TGT2 * 32 + 255) / 256, 256>>>();

    mmagemm_kernel<96, 3, 0><<<dim3((N_TGT2 + 127) / 128, 2), 256, SMEM96_3>>>(
        a2hi, a2lo, (const __half*)0, (const __half*)0, w2hi, w2lo, bl2, N_TGT2, 384, 192,
        (float*)0, 0,
        (__half*)0,
        a3hi, a3lo, 192, 0, N_TGT2);

    mmagemm_kernel<96, 3, 0><<<dim3((N_TGT2 + 127) / 128, 2), 256, SMEM96_3>>>(
        a3hi, a3lo, (const __half*)0, (const __half*)0, w3hi, w3lo, b1, N_TGT2, 192, 192,
        out_emb, 0,
        (__half*)0,
        a4hi, a4lo, 192, 0, N_TGT2);

    gemm_softmax_kernel<<<(N_TGT2 + 127) / 128, 256, SMEM128_3>>>(
        a4hi, a4lo, w4hi, w4lo, b2, N_TGT2, 192, out_ls);
}

// round 17
// speedup vs baseline: 1.1572x; 1.0033x over previous
#include <cuda_runtime.h>
#include <cuda_fp16.h>
#include <math.h>
#include <stdint.h>

#define N_SRC1 200000
#define N_TGT1 50000
#define N_TGT2 10000
#define E1 1000000
#define E2 300000
#define F_IN 256
#define F_HID 192
#define F_OUT 128

// ---------------- scratch ----------------
__device__ int g_zb[N_TGT1 + N_TGT2 + 2];
#define g_deg1 (g_zb)
#define g_deg2 (g_zb + N_TGT1)
#define g_ctr  (g_zb + N_TGT1 + N_TGT2)

__device__ int g_off1[N_TGT1 + 1];
__device__ int g_pos1[N_TGT1];
__device__ int g_idx1[E1];

__device__ int g_off2[N_TGT2 + 1];
__device__ int g_pos2[N_TGT2];
__device__ int g_idx2[E2];

__device__ int g_bsum1[256];
__device__ int g_bsum2[256];

__device__ __align__(16) __half g_xhi[(size_t)N_SRC1 * 256];

// layer-1 A: agg-hi only (K<256); x-hi half comes straight from g_xhi
__device__ __align__(16) __half g_a1hi[(size_t)N_TGT1 * 256];
__device__ __align__(16) __half g_whi[(size_t)F_HID * 512];

__device__ __align__(16) __half g_a2hi[(size_t)N_TGT2 * 384];
__device__ __align__(16) __half g_a2lo[(size_t)N_TGT2 * 384];
__device__ __align__(16) __half g_w2hi[(size_t)F_HID * 384];
__device__ __align__(16) __half g_w2lo[(size_t)F_HID * 384];

__device__ __align__(16) __half g_a3hi[(size_t)N_TGT2 * 192];
__device__ __align__(16) __half g_a3lo[(size_t)N_TGT2 * 192];
__device__ __align__(16) __half g_w3hi[(size_t)F_HID * 192];
__device__ __align__(16) __half g_w3lo[(size_t)F_HID * 192];

__device__ __align__(16) __half g_a4hi[(size_t)N_TGT2 * 192];
__device__ __align__(16) __half g_a4lo[(size_t)N_TGT2 * 192];
__device__ __align__(16) __half g_w4hi[(size_t)F_OUT * 192];
__device__ __align__(16) __half g_w4lo[(size_t)F_OUT * 192];

__device__ __align__(16) __half g_h1h[(size_t)N_TGT1 * F_HID];

__device__ __forceinline__ void split1(float a, __half& h, __half& l) {
    h = __float2half_rn(a);
    l = __float2half_rn(a - __half2float(h));
}

union H8 { __half h[8]; uint4 u; };

// ============ launch 1 (fused): hist interleaved + converts (x-hi only now) ============
#define XU (N_SRC1 * 32)
#define WQ 58368
#define HN ((E1 + E2) / 4)
__global__ void fused_pre_kernel(const float* __restrict__ x,
                                 const float* __restrict__ Wl1, const float* __restrict__ Wr1,
                                 const float* __restrict__ Wl2, const float* __restrict__ Wr2,
                                 const float* __restrict__ W1, const float* __restrict__ W2,
                                 const int* __restrict__ ei1, const int* __restrict__ ei2) {
    int i = blockIdx.x * blockDim.x + threadIdx.x;

    if (i < HN) {
        const int n1 = E1 / 4;
        if (i < n1) {
            int4 t = *(const int4*)(ei1 + E1 + i * 4);
            atomicAdd(&g_deg1[t.x], 1);
            atomicAdd(&g_deg1[t.y], 1);
            atomicAdd(&g_deg1[t.z], 1);
            atomicAdd(&g_deg1[t.w], 1);
        } else {
            int j = i - n1;
            int4 t = *(const int4*)(ei2 + E2 + j * 4);
            atomicAdd(&g_deg2[t.x], 1);
            atomicAdd(&g_deg2[t.y], 1);
            atomicAdd(&g_deg2[t.z], 1);
            atomicAdd(&g_deg2[t.w], 1);
        }
    }

    if (i < XU) {
        int r = i >> 5, c8 = (i & 31) << 3;
        const float4* xr = (const float4*)(x + (size_t)r * F_IN + c8);
        float4 va = xr[0], vb = xr[1];
        float f[8] = {va.x, va.y, va.z, va.w, vb.x, vb.y, vb.z, vb.w};
        H8 hi;
        #pragma unroll
        for (int j = 0; j < 8; j++) hi.h[j] = __float2half_rn(f[j]);
        *(uint4*)(g_xhi + (size_t)r * 256 + c8) = hi.u;
        return;
    }
    int k = i - XU;
    if (k < WQ) {
        const float* in; __half* hi; __half* lo;
        int q, c4n, lda, col0;
        if (k < 12288)      { in = Wl1; hi = g_whi;  lo = (__half*)0; q = k;          c4n = 64; lda = 512; col0 = 0; }
        else if (k < 24576) { in = Wr1; hi = g_whi;  lo = (__half*)0; q = k - 12288;  c4n = 64; lda = 512; col0 = 256; }
        else if (k < 33792) { in = Wl2; hi = g_w2hi; lo = g_w2lo;     q = k - 24576;  c4n = 48; lda = 384; col0 = 0; }
        else if (k < 43008) { in = Wr2; hi = g_w2hi; lo = g_w2lo;     q = k - 33792;  c4n = 48; lda = 384; col0 = 192; }
        else if (k < 52224) { in = W1;  hi = g_w3hi; lo = g_w3lo;     q = k - 43008;  c4n = 48; lda = 192; col0 = 0; }
        else                { in = W2;  hi = g_w4hi; lo = g_w4lo;     q = k - 52224;  c4n = 48; lda = 192; col0 = 0; }
        int r = q / c4n, c = (q % c4n) << 2;
        float4 v = *(const float4*)(in + (size_t)r * (c4n * 4) + c);
        __half h0, h1, h2, h3, l0, l1, l2, l3;
        split1(v.x, h0, l0); split1(v.y, h1, l1);
        split1(v.z, h2, l2); split1(v.w, h3, l3);
        size_t o = (size_t)r * lda + col0 + c;
        *(__half2*)(hi + o)     = __halves2half2(h0, h1);
        *(__half2*)(hi + o + 2) = __halves2half2(h2, h3);
        if (lo) {
            *(__half2*)(lo + o)     = __halves2half2(l0, l1);
            *(__half2*)(lo + o + 2) = __halves2half2(l2, l3);
        }
    }
}

// ============ per-block scans; block base via atomic counter ============
__global__ void scan_block_both_kernel(int nb1) {
    const int* deg; int* off; int* pos; int* bsum; int n; int b; int list;
    if ((int)blockIdx.x < nb1) { deg = g_deg1; off = g_off1; pos = g_pos1; bsum = g_bsum1; n = N_TGT1; b = blockIdx.x; list = 0; }
    else { deg = g_deg2; off = g_off2; pos = g_pos2; bsum = g_bsum2; n = N_TGT2; b = blockIdx.x - nb1; list = 1; }
    __shared__ int wsum[16];
    int tid = threadIdx.x, lane = tid & 31, wid = tid >> 5;
    int i = b * 512 + tid;
    int v = (i < n) ? deg[i] : 0;
    int sc = v;
    #pragma unroll
    for (int o = 1; o < 32; o <<= 1) {
        int t = __shfl_up_sync(0xFFFFFFFFu, sc, o);
        if (lane >= o) sc += t;
    }
    if (lane == 31) wsum[wid] = sc;
    __syncthreads();
    if (wid == 0) {
        int ws = (lane < 16) ? wsum[lane] : 0;
        #pragma unroll
        for (int o = 1; o < 16; o <<= 1) {
            int t = __shfl_up_sync(0xFFFFFFFFu, ws, o);
            if (lane >= o) ws += t;
        }
        if (lane < 16) wsum[lane] = ws;
    }
    __syncthreads();
    int incl = sc + (wid ? wsum[wid - 1] : 0);
    if (i < n) { off[i + 1] = incl; pos[i] = incl - v; }
    if (tid == 511) {
        int base = atomicAdd(&g_ctr[list], incl);
        bsum[b] = base;
    }
}

// ============ fill CSR, 4 edges/thread ============
__global__ void fill_both_kernel(const int* __restrict__ ei1, const int* __restrict__ ei2) {
    int i = blockIdx.x * blockDim.x + threadIdx.x;
    const int n1 = E1 / 4, n2 = E2 / 4;
    if (i < n1) {
        int4 t = *(const int4*)(ei1 + E1 + i * 4);
        int4 s = *(const int4*)(ei1 + i * 4);
        int p0 = atomicAdd(&g_pos1[t.x], 1) + g_bsum1[t.x >> 9];
        int p1 = atomicAdd(&g_pos1[t.y], 1) + g_bsum1[t.y >> 9];
        int p2 = atomicAdd(&g_pos1[t.z], 1) + g_bsum1[t.z >> 9];
        int p3 = atomicAdd(&g_pos1[t.w], 1) + g_bsum1[t.w >> 9];
        g_idx1[p0] = s.x; g_idx1[p1] = s.y; g_idx1[p2] = s.z; g_idx1[p3] = s.w;
    } else if (i < n1 + n2) {
        int j = i - n1;
        int4 t = *(const int4*)(ei2 + E2 + j * 4);
        int4 s = *(const int4*)(ei2 + j * 4);
        int p0 = atomicAdd(&g_pos2[t.x], 1) + g_bsum2[t.x >> 9];
        int p1 = atomicAdd(&g_pos2[t.y], 1) + g_bsum2[t.y >> 9];
        int p2 = atomicAdd(&g_pos2[t.z], 1) + g_bsum2[t.z >> 9];
        int p3 = atomicAdd(&g_pos2[t.w], 1) + g_bsum2[t.w >> 9];
        g_idx2[p0] = s.x; g_idx2[p1] = s.y; g_idx2[p2] = s.z; g_idx2[p3] = s.w;
    }
}

__device__ __forceinline__ int seg_beg(const int* off, const int* bsum, int w) {
    return (w & 511) ? off[w] + bsum[w >> 9] : bsum[w >> 9];
}
__device__ __forceinline__ int seg_end(const int* off, const int* bsum, int w) {
    return off[w + 1] + bsum[w >> 9];
}

__device__ __forceinline__ void add8(float* a, uint4 v) {
    __half2* h = (__half2*)&v;
    float2 f0 = __half22float2(h[0]);
    float2 f1 = __half22float2(h[1]);
    float2 f2 = __half22float2(h[2]);
    float2 f3 = __half22float2(h[3]);
    a[0] += f0.x; a[1] += f0.y; a[2] += f1.x; a[3] += f1.y;
    a[4] += f2.x; a[5] += f2.y; a[6] += f3.x; a[7] += f3.y;
}

// ============ layer-1 segment mean: hi-only output ============
__global__ void agg1_kernel() {
    int w = (blockIdx.x * blockDim.x + threadIdx.x) >> 5;
    int lane = threadIdx.x & 31;
    if (w >= N_TGT1) return;
    int beg = seg_beg(g_off1, g_bsum1, w);
    int end = seg_end(g_off1, g_bsum1, w);
    const uint4* base = (const uint4*)g_xhi;
    float acc[8] = {0.f, 0.f, 0.f, 0.f, 0.f, 0.f, 0.f, 0.f};
    int e = beg;
    for (; e + 4 <= end; e += 4) {
        int i0 = g_idx1[e], i1 = g_idx1[e + 1], i2 = g_idx1[e + 2], i3 = g_idx1[e + 3];
        uint4 v0 = __ldg(base + (size_t)i0 * 32 + lane);
        uint4 v1 = __ldg(base + (size_t)i1 * 32 + lane);
        uint4 v2 = __ldg(base + (size_t)i2 * 32 + lane);
        uint4 v3 = __ldg(base + (size_t)i3 * 32 + lane);
        add8(acc, v0);
        add8(acc, v1);
        add8(acc, v2);
        add8(acc, v3);
    }
    for (; e < end; e++) {
        uint4 v = __ldg(base + (size_t)g_idx1[e] * 32 + lane);
        add8(acc, v);
    }
    int c = end - beg;
    float s = 1.0f / (float)(c > 1 ? c : 1);
    H8 hi;
    #pragma unroll
    for (int j = 0; j < 8; j++) hi.h[j] = __float2half_rn(acc[j] * s);
    *(uint4*)(g_a1hi + (size_t)w * 256 + lane * 8) = hi.u;
}

// ============ layer-2 segment mean ============
__global__ void agg2_kernel() {
    int w = (blockIdx.x * blockDim.x + threadIdx.x) >> 5;
    int lane = threadIdx.x & 31;
    if (w >= N_TGT2) return;
    int beg = seg_beg(g_off2, g_bsum2, w);
    int end = seg_end(g_off2, g_bsum2, w);
    const uint4* base = (const uint4*)g_h1h;
    bool act = lane < 24;
    float acc[8] = {0.f, 0.f, 0.f, 0.f, 0.f, 0.f, 0.f, 0.f};
    int e = beg;
    for (; e + 2 <= end; e += 2) {
        int i0 = g_idx2[e], i1 = g_idx2[e + 1];
        if (act) {
            uint4 v0 = __ldg(base + (size_t)i0 * 24 + lane);
            uint4 v1 = __ldg(base + (size_t)i1 * 24 + lane);
            add8(acc, v0);
            add8(acc, v1);
        }
    }
    if (e < end && act) {
        uint4 v = __ldg(base + (size_t)g_idx2[e] * 24 + lane);
        add8(acc, v);
    }
    if (!act) return;
    int c = end - beg;
    float s = 1.0f / (float)(c > 1 ? c : 1);
    H8 hi, lo;
    #pragma unroll
    for (int j = 0; j < 8; j++) {
        float m = acc[j] * s;
        split1(m, hi.h[j], lo.h[j]);
    }
    size_t o = (size_t)w * 384 + lane * 8;
    *(uint4*)(g_a2hi + o) = hi.u;
    *(uint4*)(g_a2lo + o) = lo.u;
}

// ================= mma.sync fp16 GEMM, 3-stage pipeline =================
// TERMS: 1 = A-hi x W-hi ; 3 = (Ahi+Alo) x Whi + Ahi x Wlo
#define ROWB 80

__device__ __forceinline__ uint32_t smem_u32(const void* p) {
    uint32_t a;
    asm("{ .reg .u64 t; cvta.to.shared.u64 t, %1; cvt.u32.u64 %0, t; }" : "=r"(a) : "l"(p));
    return a;
}
__device__ __forceinline__ void cp16(uint32_t s, const void* g) {
    asm volatile("cp.async.cg.shared.global [%0], [%1], 16;" :: "r"(s), "l"(g));
}
__device__ __forceinline__ void cp_commit() { asm volatile("cp.async.commit_group;"); }
template <int N>
__device__ __forceinline__ void cp_waitg() { asm volatile("cp.async.wait_group %0;" :: "n"(N)); }
__device__ __forceinline__ void ldm4(uint32_t* r, uint32_t a) {
    asm volatile("ldmatrix.sync.aligned.m8n8.x4.shared.b16 {%0,%1,%2,%3}, [%4];"
                 : "=r"(r[0]), "=r"(r[1]), "=r"(r[2]), "=r"(r[3]) : "r"(a));
}
__device__ __forceinline__ void mma_f16(float* c, const uint32_t* a, uint32_t b0, uint32_t b1) {
    asm volatile("mma.sync.aligned.m16n8k16.row.col.f32.f16.f16.f32 "
                 "{%0,%1,%2,%3},{%4,%5,%6,%7},{%8,%9},{%0,%1,%2,%3};"
                 : "+f"(c[0]), "+f"(c[1]), "+f"(c[2]), "+f"(c[3])
                 : "r"(a[0]), "r"(a[1]), "r"(a[2]), "r"(a[3]), "r"(b0), "r"(b1));
}

template <int NN, int TERMS, int KSPLIT>
__device__ __forceinline__ void gemm_mainloop(
    uint32_t smb, int tid, int w, int lane, int m0, int M, int K,
    const __half* ahi, const __half* alo,
    const __half* ahiB, const __half* aloB,
    const __half* whi, const __half* wlo,
    float acc[2][2 * (NN / 32)][4])
{
    constexpr int NJ = NN / 32;
    constexpr int NBI = (NN + 63) / 64;
    constexpr int AR = (TERMS >= 2) ? 256 : 128;   // A smem rows (hi [+lo])
    constexpr int SAHI = 0;
    constexpr int SALO = 128 * ROWB;               // valid only when TERMS>=2
    constexpr int SBHI = AR * ROWB;
    constexpr int SBLO = (AR + NN) * ROWB;
    constexpr int BUF = (AR + (TERMS == 3 ? 2 : 1) * NN) * ROWB;

    int wm = (w >> 1) * 32;
    int wn = (w & 1) * (NN / 2);
    int arow = tid >> 2;
    int aseg = (tid & 3) * 16;
    int asegk = (tid & 3) * 8;
    int chunks = K >> 5;

    auto load_chunk = [&](int c, int buf) {
        int k0 = c * 32;
        uint32_t base = smb + buf * BUF;
        const __half* Ah; const __half* Al; int alda, koff;
        if (KSPLIT) {
            if (k0 >= 256) { Ah = ahiB; Al = aloB; alda = 256; koff = k0 - 256; }
            else           { Ah = ahi;  Al = alo;  alda = 256; koff = k0; }
        } else { Ah = ahi; Al = alo; alda = K; koff = k0; }
        #pragma unroll
        for (int i = 0; i < 2; i++) {
            int row = arow + i * 64;
            int gr = m0 + row; if (gr >= M) gr = M - 1;
            size_t go = (size_t)gr * alda + koff + asegk;
            uint32_t so = row * ROWB + aseg;
            cp16(base + SAHI + so, Ah + go);
            if (TERMS >= 2) cp16(base + SALO + so, Al + go);
        }
        #pragma unroll
        for (int i = 0; i < NBI; i++) {
            int row = arow + i * 64;
            if (row < NN) {
                size_t go = (size_t)row * K + k0 + asegk;
                uint32_t so = row * ROWB + aseg;
                cp16(base + SBHI + so, whi + go);
                if (TERMS == 3) cp16(base + SBLO + so, wlo + go);
            }
        }
    };

    int grp = lane >> 3, lr = lane & 7;
    int a_row_off = lr + (grp & 1) * 8;
    int a_k_off = (grp >> 1) * 8;
    int b_row_off = (grp & 2) * 4 + lr;
    int b_k_off = (grp & 1) * 8;

    load_chunk(0, 0);
    cp_commit();
    if (chunks > 1) { load_chunk(1, 1); cp_commit(); }

    int buf = 0;
    #pragma unroll 1
    for (int c = 0; c < chunks; c++) {
        if (c + 2 < chunks) {
            int nb = (buf + 2) % 3;
            load_chunk(c + 2, nb);
            cp_commit();
            cp_waitg<2>();
        } else if (c + 1 < chunks) {
            cp_waitg<1>();
        } else {
            cp_waitg<0>();
        }
        __syncthreads();

        uint32_t base = smb + buf * BUF;
        #pragma unroll
        for (int s = 0; s < 2; s++) {
            uint32_t ah[2][4], al[2][4];
            #pragma unroll
            for (int mt = 0; mt < 2; mt++) {
                uint32_t ra = (wm + mt * 16 + a_row_off) * ROWB + (s * 16 + a_k_off) * 2;
                ldm4(ah[mt], base + SAHI + ra);
                if (TERMS >= 2) ldm4(al[mt], base + SALO + ra);
            }
            #pragma unroll
            for (int j = 0; j < NJ; j++) {
                uint32_t rb = (wn + j * 16 + b_row_off) * ROWB + (s * 16 + b_k_off) * 2;
                uint32_t bh[4];
                ldm4(bh, base + SBHI + rb);
                #pragma unroll
                for (int mt = 0; mt < 2; mt++) {
                    mma_f16(acc[mt][2 * j],     ah[mt], bh[0], bh[1]);
                    mma_f16(acc[mt][2 * j + 1], ah[mt], bh[2], bh[3]);
                    if (TERMS >= 2) {
                        mma_f16(acc[mt][2 * j],     al[mt], bh[0], bh[1]);
                        mma_f16(acc[mt][2 * j + 1], al[mt], bh[2], bh[3]);
                    }
                }
                if (TERMS == 3) {
                    uint32_t bl[4];
                    ldm4(bl, base + SBLO + rb);
                    #pragma unroll
                    for (int mt = 0; mt < 2; mt++) {
                        mma_f16(acc[mt][2 * j],     ah[mt], bl[0], bl[1]);
                        mma_f16(acc[mt][2 * j + 1], ah[mt], bl[2], bl[3]);
                    }
                }
            }
        }
        __syncthreads();
        buf = (buf + 1) % 3;
    }
}

template <int NN, int TERMS, int KSPLIT>
__global__ __launch_bounds__(256) void mmagemm_kernel(
    const __half* __restrict__ ahi, const __half* __restrict__ alo,
    const __half* __restrict__ ahiB, const __half* __restrict__ aloB,
    const __half* __restrict__ whi, const __half* __restrict__ wlo,
    const float* __restrict__ bias, int M, int K, int NTOT,
    float* __restrict__ Cf32, int relu_f32,
    __half* __restrict__ Ch16,
    __half* __restrict__ shi, __half* __restrict__ slo,
    int s_lda, int s_col0, int s_maxrow)
{
    extern __shared__ char sm[];
    uint32_t smb = smem_u32(sm);
    int tid = threadIdx.x;
    int w = tid >> 5, lane = tid & 31;
    int m0 = blockIdx.x * 128;
    int nb = blockIdx.y * NN;
    int wm = (w >> 1) * 32;
    int wn = (w & 1) * (NN / 2);

    const __half* whi_s = whi + (size_t)nb * K;
    const __half* wlo_s = wlo ? wlo + (size_t)nb * K : wlo;

    float acc[2][2 * (NN / 32)][4];
    #pragma unroll
    for (int i = 0; i < 2; i++)
        #pragma unroll
        for (int j = 0; j < 2 * (NN / 32); j++)
            #pragma unroll
            for (int k = 0; k < 4; k++) acc[i][j][k] = 0.f;

    gemm_mainloop<NN, TERMS, KSPLIT>(smb, tid, w, lane, m0, M, K, ahi, alo, ahiB, aloB, whi_s, wlo_s, acc);

    int g = lane >> 2, t = lane & 3;
    #pragma unroll
    for (int mt = 0; mt < 2; mt++) {
        int r0 = m0 + wm + mt * 16 + g;
        #pragma unroll
        for (int j = 0; j < 2 * (NN / 32); j++) {
            int col = nb + wn + j * 8 + 2 * t;
            float2 bv = *(const float2*)(bias + col);
            float o0 = acc[mt][j][0] + bv.x, o1 = acc[mt][j][1] + bv.y;
            float o2 = acc[mt][j][2] + bv.x, o3 = acc[mt][j][3] + bv.y;
            if (Cf32) {
                float p0 = o0, p1 = o1, p2 = o2, p3 = o3;
                if (relu_f32) {
                    p0 = fmaxf(p0, 0.f); p1 = fmaxf(p1, 0.f);
                    p2 = fmaxf(p2, 0.f); p3 = fmaxf(p3, 0.f);
                }
                if (r0 < M)     *(float2*)(Cf32 + (size_t)r0 * NTOT + col)       = make_float2(p0, p1);
                if (r0 + 8 < M) *(float2*)(Cf32 + (size_t)(r0 + 8) * NTOT + col) = make_float2(p2, p3);
            }
            if (Ch16) {
                float p0 = fmaxf(o0, 0.f), p1 = fmaxf(o1, 0.f);
                float p2 = fmaxf(o2, 0.f), p3 = fmaxf(o3, 0.f);
                if (r0 < M)
                    *(__half2*)(Ch16 + (size_t)r0 * NTOT + col) =
                        __halves2half2(__float2half_rn(p0), __float2half_rn(p1));
                if (r0 + 8 < M)
                    *(__half2*)(Ch16 + (size_t)(r0 + 8) * NTOT + col) =
                        __halves2half2(__float2half_rn(p2), __float2half_rn(p3));
            }
            if (shi) {
                o0 = fmaxf(o0, 0.f); o1 = fmaxf(o1, 0.f);
                o2 = fmaxf(o2, 0.f); o3 = fmaxf(o3, 0.f);
                __half h0, h1, h2, h3, l0, l1, l2, l3;
                split1(o0, h0, l0); split1(o1, h1, l1);
                split1(o2, h2, l2); split1(o3, h3, l3);
                if (r0 < s_maxrow) {
                    size_t o = (size_t)r0 * s_lda + s_col0 + col;
                    *(__half2*)(shi + o) = __halves2half2(h0, h1);
                    *(__half2*)(slo + o) = __halves2half2(l0, l1);
                }
                if (r0 + 8 < s_maxrow) {
                    size_t o = (size_t)(r0 + 8) * s_lda + s_col0 + col;
                    *(__half2*)(shi + o) = __halves2half2(h2, h3);
                    *(__half2*)(slo + o) = __halves2half2(l2, l3);
                }
            }
        }
    }
}

// ============ gemm (NN=128, TERMS=3) fused with log_softmax epilogue ============
__global__ __launch_bounds__(256) void gemm_softmax_kernel(
    const __half* __restrict__ ahi, const __half* __restrict__ alo,
    const __half* __restrict__ whi, const __half* __restrict__ wlo,
    const float* __restrict__ bias, int M, int K,
    float* __restrict__ out)
{
    extern __shared__ char sm[];
    uint32_t smb = smem_u32(sm);
    int tid = threadIdx.x;
    int w = tid >> 5, lane = tid & 31;
    int m0 = blockIdx.x * 128;
    int wm = (w >> 1) * 32;
    int wn = (w & 1) * 64;

    float acc[2][8][4];
    #pragma unroll
    for (int i = 0; i < 2; i++)
        #pragma unroll
        for (int j = 0; j < 8; j++)
            #pragma unroll
            for (int k = 0; k < 4; k++) acc[i][j][k] = 0.f;

    gemm_mainloop<128, 3, 0>(smb, tid, w, lane, m0, M, K, ahi, alo, ahi, alo, whi, wlo, acc);

    float* es = (float*)sm;
    int g = lane >> 2, t = lane & 3;
    #pragma unroll
    for (int mt = 0; mt < 2; mt++) {
        int r = wm + mt * 16 + g;
        #pragma unroll
        for (int j = 0; j < 8; j++) {
            int col = wn + j * 8 + 2 * t;
            float2 bv = *(const float2*)(bias + col);
            *(float2*)&es[(r)     * 132 + col] = make_float2(acc[mt][j][0] + bv.x, acc[mt][j][1] + bv.y);
            *(float2*)&es[(r + 8) * 132 + col] = make_float2(acc[mt][j][2] + bv.x, acc[mt][j][3] + bv.y);
        }
    }
    __syncthreads();

    for (int rr = 0; rr < 16; rr++) {
        int r = w * 16 + rr;
        int gr = m0 + r;
        if (gr >= M) break;
        float4 v = *(float4*)&es[r * 132 + lane * 4];
        float m = fmaxf(fmaxf(v.x, v.y), fmaxf(v.z, v.w));
        #pragma unroll
        for (int o = 16; o > 0; o >>= 1) m = fmaxf(m, __shfl_xor_sync(0xFFFFFFFFu, m, o));
        float s = expf(v.x - m) + expf(v.y - m) + expf(v.z - m) + expf(v.w - m);
        #pragma unroll
        for (int o = 16; o > 0; o >>= 1) s += __shfl_xor_sync(0xFFFFFFFFu, s, o);
        float l = m + logf(s);
        *(float4*)(out + (size_t)gr * F_OUT + lane * 4) =
            make_float4(v.x - l, v.y - l, v.z - l, v.w - l);
    }
}

// ---------------- launch ----------------
extern "C" void kernel_launch(void* const* d_in, const int* in_sizes, int n_in,
                              void* d_out, int out_size) {
    const float* x   = (const float*)d_in[0];
    const int*   ei1 = (const int*)d_in[1];
    const int*   ei2 = (const int*)d_in[2];
    const float* Wl1 = (const float*)d_in[3];
    const float* bl1 = (const float*)d_in[4];
    const float* Wr1 = (const float*)d_in[5];
    const float* Wl2 = (const float*)d_in[6];
    const float* bl2 = (const float*)d_in[7];
    const float* Wr2 = (const float*)d_in[8];
    const float* W1  = (const float*)d_in[9];
    const float* b1  = (const float*)d_in[10];
    const float* W2  = (const float*)d_in[11];
    const float* b2  = (const float*)d_in[12];

    float* out = (float*)d_out;
    float* out_ls  = out;
    float* out_emb = out + (size_t)N_TGT2 * F_OUT;

    int* zb;
    __half *xhi, *a1hi, *whi, *h1h;
    __half *a2hi, *a2lo, *w2hi, *w2lo;
    __half *a3hi, *a3lo, *w3hi, *w3lo;
    __half *a4hi, *a4lo, *w4hi, *w4lo;
    cudaGetSymbolAddress((void**)&zb, g_zb);
    cudaGetSymbolAddress((void**)&xhi, g_xhi);
    cudaGetSymbolAddress((void**)&a1hi, g_a1hi);
    cudaGetSymbolAddress((void**)&whi, g_whi);
    cudaGetSymbolAddress((void**)&h1h, g_h1h);
    cudaGetSymbolAddress((void**)&a2hi, g_a2hi);
    cudaGetSymbolAddress((void**)&a2lo, g_a2lo);
    cudaGetSymbolAddress((void**)&w2hi, g_w2hi);
    cudaGetSymbolAddress((void**)&w2lo, g_w2lo);
    cudaGetSymbolAddress((void**)&a3hi, g_a3hi);
    cudaGetSymbolAddress((void**)&a3lo, g_a3lo);
    cudaGetSymbolAddress((void**)&w3hi, g_w3hi);
    cudaGetSymbolAddress((void**)&w3lo, g_w3lo);
    cudaGetSymbolAddress((void**)&a4hi, g_a4hi);
    cudaGetSymbolAddress((void**)&a4lo, g_a4lo);
    cudaGetSymbolAddress((void**)&w4hi, g_w4hi);
    cudaGetSymbolAddress((void**)&w4lo, g_w4lo);

    const int SMEM192_1 = 3 * (128 + 192) * ROWB;     // 76800
    const int SMEM96_3  = 3 * (256 + 2 * 96) * ROWB;  // 107520
    const int SMEM128_3 = 3 * (256 + 2 * 128) * ROWB; // 122880
    cudaFuncSetAttribute((const void*)mmagemm_kernel<192, 1, 1>, cudaFuncAttributeMaxDynamicSharedMemorySize, SMEM192_1);
    cudaFuncSetAttribute((const void*)mmagemm_kernel<96, 3, 0>, cudaFuncAttributeMaxDynamicSharedMemorySize, SMEM96_3);
    cudaFuncSetAttribute((const void*)gemm_softmax_kernel, cudaFuncAttributeMaxDynamicSharedMemorySize, SMEM128_3);

    int nb1 = (N_TGT1 + 511) / 512;
    int nb2 = (N_TGT2 + 511) / 512;

    cudaMemsetAsync(zb, 0, (N_TGT1 + N_TGT2 + 2) * sizeof(int), 0);

    {
        int total = XU + WQ;
        fused_pre_kernel<<<(total + 255) / 256, 256>>>(x, Wl1, Wr1, Wl2, Wr2, W1, W2, ei1, ei2);
    }
    scan_block_both_kernel<<<nb1 + nb2, 512>>>(nb1);
    fill_both_kernel<<<((E1 + E2) / 4 + 255) / 256, 256>>>(ei1, ei2);

    agg1_kernel<<<(N_TGT1 * 32 + 255) / 256, 256>>>();

    // layer-1 GEMM (1-term pure fp16, split-A: agg-hi | x-hi)
    mmagemm_kernel<192, 1, 1><<<dim3((N_TGT1 + 127) / 128, 1), 256, SMEM192_1>>>(
        a1hi, (const __half*)0, xhi, (const __half*)0, whi, (const __half*)0,
        bl1, N_TGT1, 512, 192,
        (float*)0, 0,
        h1h,
        a2hi, a2lo, 384, 192, N_TGT2);

    agg2_kernel<<<(N_TGT2 * 32 + 255) / 256, 256>>>();

    mmagemm_kernel<96, 3, 0><<<dim3((N_TGT2 + 127) / 128, 2), 256, SMEM96_3>>>(
        a2hi, a2lo, (const __half*)0, (const __half*)0, w2hi, w2lo, bl2, N_TGT2, 384, 192,
        (float*)0, 0,
        (__half*)0,
        a3hi, a3lo, 192, 0, N_TGT2);

    mmagemm_kernel<96, 3, 0><<<dim3((N_TGT2 + 127) / 128, 2), 256, SMEM96_3>>>(
        a3hi, a3lo, (const __half*)0, (const __half*)0, w3hi, w3lo, b1, N_TGT2, 192, 192,
        out_emb, 0,
        (__half*)0,
        a4hi, a4lo, 192, 0, N_TGT2);

    gemm_softmax_kernel<<<(N_TGT2 + 127) / 128, 256, SMEM128_3>>>(
        a4hi, a4lo, w4hi, w4lo, b2, N_TGT2, 192, out_ls);
}